// round 11
// baseline (speedup 1.0000x reference)
#include <cuda_runtime.h>
#include <cuda_fp16.h>
#include <cstdint>

#define NUM_T 64
#define DIN   4096
#define DOUT  11008
#define KS    4
#define KPER  (DIN / KS)       // 1024
#define KC    128
#define NCHUNK (KPER / KC)     // 8
#define NT    64
#define SSTRIDE 136            // 128 halves + 8 pad: 272B rows, conflict-free ldmatrix
#define XHALVES (NUM_T * SSTRIDE)          // 8704
#define STAGE_HALVES (2 * XHALVES)         // X tile + W tile
#define STAGE_B (STAGE_HALVES * 2)         // 34816 bytes
#define SMEM_TOTAL (2 * STAGE_B)           // 69632 bytes

// Scratch (allocation-free rule: __device__ globals)
__device__ __align__(256) __half g_xq[NUM_T * DIN];
__device__ __align__(256) float  g_part[KS * NUM_T * DOUT];   // 11.27 MB

// ---------------------------------------------------------------------------
// MXFP4 block constants from amax (integer bit-pattern construction)
// ---------------------------------------------------------------------------
__device__ __forceinline__ void mk_consts(float amax, float& c6s, float& cM,
                                          uint32_t& c2s_bits) {
    if (!(amax > 0.0f)) amax = 1.0f;
    int e  = ((__float_as_int(amax) >> 23) & 0xFF) - 127;
    int se = min(max(e - 2, -127), 127);
    c6s = __int_as_float(((se + 129) << 23) | 0x400000);   // 6 * 2^se
    cM  = __int_as_float((se + 149) << 23);                // 2^(se+22) magic
    c2s_bits = (uint32_t)((se + 128) << 23);               // bits of 2^(se+1)
}

// E2M1 qdq in the t-domain; exactly matches reference (rel_err 0.0 proven).
__device__ __forceinline__ float qdq_fast(float t, float c6s, float cM,
                                          uint32_t c2s_bits) {
    float a = fminf(fabsf(t), c6s);
    uint32_t u = __float_as_uint(a);
    uint32_t r1 = (u + 0x1FFFFFu + ((u >> 22) & 1u)) & 0xFFC00000u;
    float q2 = __fadd_rn(__fadd_rn(a, cM), -cM);
    uint32_t q = (u < c2s_bits) ? __float_as_uint(q2) : r1;
    return __uint_as_float(q | (__float_as_uint(t) & 0x80000000u));
}

// pack two exact f32 values into f16x2 (lo = x, hi = y); conversion exact
__device__ __forceinline__ uint32_t pack_h2(float x, float y) {
    uint32_t r;
    asm("cvt.rn.f16x2.f32 %0, %1, %2;" : "=r"(r) : "f"(y), "f"(x));
    return r;
}

// ---------------------------------------------------------------------------
// x quant-dequant -> f16 (one MXFP block = 8 lanes x float4)
// ---------------------------------------------------------------------------
__global__ void qdq_x_kernel(const float* __restrict__ in) {
    int gtid = blockIdx.x * blockDim.x + threadIdx.x;
    int warp = gtid >> 5;
    int lane = threadIdx.x & 31;
    long base = (long)warp * 128 + (long)lane * 4;
    if (base >= NUM_T * DIN) return;
    float4 v = *reinterpret_cast<const float4*>(in + base);
    float am = fmaxf(fmaxf(fabsf(v.x), fabsf(v.y)), fmaxf(fabsf(v.z), fabsf(v.w)));
    am = fmaxf(am, __shfl_xor_sync(0xffffffffu, am, 1));
    am = fmaxf(am, __shfl_xor_sync(0xffffffffu, am, 2));
    am = fmaxf(am, __shfl_xor_sync(0xffffffffu, am, 4));
    float c6s, cM; uint32_t c2sb;
    mk_consts(am, c6s, cM, c2sb);
    uint2 st;
    st.x = pack_h2(qdq_fast(v.x, c6s, cM, c2sb), qdq_fast(v.y, c6s, cM, c2sb));
    st.y = pack_h2(qdq_fast(v.z, c6s, cM, c2sb), qdq_fast(v.w, c6s, cM, c2sb));
    *reinterpret_cast<uint2*>(&g_xq[base]) = st;
}

// ---------------------------------------------------------------------------
// Fused GEMM: CTA 64M x 64N x KPER, 256 thr, KC=128 chunks (8 barriers).
// One full MXFP block (32 W floats) per thread per chunk: thread-local amax,
// no shfl. X staged via cp.async. Double-buffered, one bar per chunk.
// ---------------------------------------------------------------------------
#define LDMATRIX_X4(r0, r1, r2, r3, addr)                                        \
    asm volatile("ldmatrix.sync.aligned.m8n8.x4.shared.b16 {%0,%1,%2,%3}, [%4];" \
                 : "=r"(r0), "=r"(r1), "=r"(r2), "=r"(r3) : "r"(addr))

#define MMA16816(c, a0, a1, a2, a3, b0, b1)                                   \
    asm volatile("mma.sync.aligned.m16n8k16.row.col.f32.f16.f16.f32 "         \
                 "{%0,%1,%2,%3}, {%4,%5,%6,%7}, {%8,%9}, {%0,%1,%2,%3};"      \
                 : "+f"(c[0]), "+f"(c[1]), "+f"(c[2]), "+f"(c[3])             \
                 : "r"(a0), "r"(a1), "r"(a2), "r"(a3), "r"(b0), "r"(b1))

__global__ __launch_bounds__(256) void fused_gemm_kernel(const float* __restrict__ W) {
    extern __shared__ __half sm[];   // per stage: X [64][136] then W [64][136]
    int tid  = threadIdx.x;
    int w    = tid >> 5;
    int lane = tid & 31;
    int nbase = blockIdx.x * NT;
    int kbase = blockIdx.y * KPER;
    int mrow  = (w >> 1) * 16;     // 4 M-groups of 16
    int ncol  = (w & 1) * 32;      // 2 N-groups of 32

    float acc[4][4];
    #pragma unroll
    for (int i = 0; i < 4; i++)
        #pragma unroll
        for (int j = 0; j < 4; j++) acc[i][j] = 0.0f;

    int q = lane >> 3, li = lane & 7;
    uint32_t a_base = (uint32_t)__cvta_generic_to_shared(
        &sm[(mrow + (q & 1) * 8 + li) * SSTRIDE + (q >> 1) * 8]);
    uint32_t b_base = (uint32_t)__cvta_generic_to_shared(
        &sm[XHALVES + (ncol + (q >> 1) * 8 + li) * SSTRIDE + (q & 1) * 8]);

    // W map: 4 threads per row, one full 32-float MXFP block each
    int wrow = tid >> 2;
    int wcol = (tid & 3) << 5;     // 0,32,64,96
    const float* wp = W + (size_t)(nbase + wrow) * DIN + kbase + wcol;
    // X map: 4 threads per row, 32 halves (64B) each
    int xr = tid >> 2, xch = (tid & 3) << 5;
    const __half* xp = g_xq + xr * DIN + kbase + xch;
    uint32_t xdst0 = (uint32_t)__cvta_generic_to_shared(&sm[xr * SSTRIDE + xch]);

    float4 wv[8];

    auto loadw = [&](int c) {
        #pragma unroll
        for (int j = 0; j < 8; j++)
            wv[j] = reinterpret_cast<const float4*>(wp + c * KC)[j];
    };
    auto cpasync_x = [&](int c) {
        uint32_t d = xdst0 + (c & 1) * STAGE_B;
        const __half* s = xp + c * KC;
        asm volatile(
            "cp.async.ca.shared.global [%0], [%1], 16;\n\t"
            "cp.async.ca.shared.global [%2], [%3], 16;\n\t"
            "cp.async.ca.shared.global [%4], [%5], 16;\n\t"
            "cp.async.ca.shared.global [%6], [%7], 16;\n\t"
            "cp.async.commit_group;"
            :: "r"(d), "l"(s), "r"(d + 16), "l"(s + 8),
               "r"(d + 32), "l"(s + 16), "r"(d + 48), "l"(s + 24) : "memory");
    };
    auto stagew = [&](int s) {
        float am = 0.0f;
        #pragma unroll
        for (int j = 0; j < 8; j++)
            am = fmaxf(am, fmaxf(fmaxf(fabsf(wv[j].x), fabsf(wv[j].y)),
                                 fmaxf(fabsf(wv[j].z), fabsf(wv[j].w))));
        float c6s, cM; uint32_t c2sb;
        mk_consts(am, c6s, cM, c2sb);   // thread-local: no shfl
        __half* wr = &sm[s * STAGE_HALVES + XHALVES + wrow * SSTRIDE + wcol];
        #pragma unroll
        for (int j = 0; j < 8; j += 2) {
            uint4 st;
            st.x = pack_h2(qdq_fast(wv[j].x,   c6s, cM, c2sb), qdq_fast(wv[j].y,   c6s, cM, c2sb));
            st.y = pack_h2(qdq_fast(wv[j].z,   c6s, cM, c2sb), qdq_fast(wv[j].w,   c6s, cM, c2sb));
            st.z = pack_h2(qdq_fast(wv[j+1].x, c6s, cM, c2sb), qdq_fast(wv[j+1].y, c6s, cM, c2sb));
            st.w = pack_h2(qdq_fast(wv[j+1].z, c6s, cM, c2sb), qdq_fast(wv[j+1].w, c6s, cM, c2sb));
            *reinterpret_cast<uint4*>(wr + j * 4) = st;
        }
    };

    // -------- prologue --------
    cpasync_x(0);
    loadw(0);
    stagew(0);
    loadw(1);
    asm volatile("cp.async.wait_group 0;" ::: "memory");
    __syncthreads();

    // -------- main loop: one barrier per chunk --------
    #pragma unroll 1
    for (int c = 0; c < NCHUNK; c++) {
        if (c + 1 < NCHUNK) {
            cpasync_x(c + 1);          // overlaps with quant below
            stagew((c + 1) & 1);       // quant wv (chunk c+1) into other stage
        }
        if (c + 2 < NCHUNK)
            loadw(c + 2);
        uint32_t off = (c & 1) * STAGE_B;
        #pragma unroll
        for (int ks = 0; ks < 8; ks++) {
            uint32_t a0, a1, a2, a3;
            LDMATRIX_X4(a0, a1, a2, a3, a_base + off + ks * 32);
            #pragma unroll
            for (int nb = 0; nb < 2; nb++) {
                uint32_t b0, b1, b2, b3;
                LDMATRIX_X4(b0, b1, b2, b3,
                            b_base + off + nb * (16 * SSTRIDE * 2) + ks * 32);
                MMA16816(acc[nb * 2 + 0], a0, a1, a2, a3, b0, b1);
                MMA16816(acc[nb * 2 + 1], a0, a1, a2, a3, b2, b3);
            }
        }
        asm volatile("cp.async.wait_group 0;" ::: "memory");
        __syncthreads();
    }

    // epilogue: fp32 partials. Warp tile 16x32 at (mrow, nbase+ncol).
    float* pb = g_part + (size_t)blockIdx.y * NUM_T * DOUT;
    int tg = lane >> 2, tig = lane & 3;
    #pragma unroll
    for (int nf = 0; nf < 4; nf++) {
        int col = nbase + ncol + nf * 8 + tig * 2;
        int r0  = mrow + tg;
        *reinterpret_cast<float2*>(&pb[(size_t)r0 * DOUT + col]) =
            make_float2(acc[nf][0], acc[nf][1]);
        *reinterpret_cast<float2*>(&pb[(size_t)(r0 + 8) * DOUT + col]) =
            make_float2(acc[nf][2], acc[nf][3]);
    }
}

// ---------------------------------------------------------------------------
// Reduce K-splits + bias qdq. 1 thread = 1 float4 of output.
// ---------------------------------------------------------------------------
__global__ void reduce_bias_kernel(const float* __restrict__ bias, float* __restrict__ out) {
    int t  = blockIdx.x * blockDim.x + threadIdx.x;
    int m  = t / (DOUT / 4);
    int o  = (t % (DOUT / 4)) * 4;

    float4 b4 = *reinterpret_cast<const float4*>(bias + o);
    float am = fmaxf(fmaxf(fabsf(b4.x), fabsf(b4.y)), fmaxf(fabsf(b4.z), fabsf(b4.w)));
    am = fmaxf(am, __shfl_xor_sync(0xffffffffu, am, 1));
    am = fmaxf(am, __shfl_xor_sync(0xffffffffu, am, 2));
    am = fmaxf(am, __shfl_xor_sync(0xffffffffu, am, 4));
    float c6s, cM; uint32_t c2sb;
    mk_consts(am, c6s, cM, c2sb);

    size_t idx = (size_t)m * DOUT + o;
    const size_t ps = (size_t)NUM_T * DOUT;
    float4 r;
    r.x = qdq_fast(b4.x, c6s, cM, c2sb);
    r.y = qdq_fast(b4.y, c6s, cM, c2sb);
    r.z = qdq_fast(b4.z, c6s, cM, c2sb);
    r.w = qdq_fast(b4.w, c6s, cM, c2sb);
    #pragma unroll
    for (int s = 0; s < KS; s++) {
        float4 p = *reinterpret_cast<const float4*>(g_part + s * ps + idx);
        r.x += p.x; r.y += p.y; r.z += p.z; r.w += p.w;
    }
    *reinterpret_cast<float4*>(out + idx) = r;
}

// ---------------------------------------------------------------------------
extern "C" void kernel_launch(void* const* d_in, const int* in_sizes, int n_in,
                              void* d_out, int out_size) {
    const float* x = nullptr;
    const float* wgt = nullptr;
    const float* bias = nullptr;
    for (int i = 0; i < n_in; i++) {
        if (in_sizes[i] == NUM_T * DIN)     x    = (const float*)d_in[i];
        else if (in_sizes[i] == DOUT * DIN) wgt  = (const float*)d_in[i];
        else if (in_sizes[i] == DOUT)       bias = (const float*)d_in[i];
    }
    float* out = (float*)d_out;

    cudaFuncSetAttribute(fused_gemm_kernel,
                         cudaFuncAttributeMaxDynamicSharedMemorySize, SMEM_TOTAL);

    qdq_x_kernel<<<NUM_T * DIN / 4 / 128, 128>>>(x);
    fused_gemm_kernel<<<dim3(DOUT / NT, KS), 256, SMEM_TOTAL>>>(wgt);
    reduce_bias_kernel<<<(NUM_T * DOUT / 4) / 256, 256>>>(bias, out);
    (void)out_size;
}

// round 12
// speedup vs baseline: 1.1924x; 1.1924x over previous
#include <cuda_runtime.h>
#include <cuda_fp16.h>
#include <cstdint>

#define NUM_T 64
#define DIN   4096
#define DOUT  11008
#define KS    4
#define KPER  (DIN / KS)       // 1024
#define KC    64
#define NCHUNK (KPER / KC)     // 16
#define NT    64
#define SSTRIDE 72             // +8 half pad: 144B rows, conflict-free ldmatrix
// f16 region: stage s at s*18432B; X tile at +0, W tile at +9216B
#define F16_STAGE_B 18432
#define XW_OFF      9216
// raw W ring: 3 stages of 256 threads x 80B slots
#define RAW_OFF     36864
#define RAW_STAGE_B 20480
#define SMEM_TOTAL  (RAW_OFF + 3 * RAW_STAGE_B)   // 98304 (96KB) -> 2 CTAs/SM

// Scratch (allocation-free rule: __device__ globals)
__device__ __align__(256) __half g_xq[NUM_T * DIN];
__device__ __align__(256) float  g_part[KS * NUM_T * DOUT];   // 11.27 MB

// ---------------------------------------------------------------------------
// MXFP4 block constants from amax (integer bit-pattern construction)
// ---------------------------------------------------------------------------
__device__ __forceinline__ void mk_consts(float amax, float& c6s, float& cM,
                                          uint32_t& c2s_bits) {
    if (!(amax > 0.0f)) amax = 1.0f;
    int e  = ((__float_as_int(amax) >> 23) & 0xFF) - 127;
    int se = min(max(e - 2, -127), 127);
    c6s = __int_as_float(((se + 129) << 23) | 0x400000);   // 6 * 2^se
    cM  = __int_as_float((se + 149) << 23);                // 2^(se+22) magic
    c2s_bits = (uint32_t)((se + 128) << 23);               // bits of 2^(se+1)
}

// E2M1 qdq in the t-domain; exactly matches reference (rel_err 0.0 proven).
__device__ __forceinline__ float qdq_fast(float t, float c6s, float cM,
                                          uint32_t c2s_bits) {
    float a = fminf(fabsf(t), c6s);
    uint32_t u = __float_as_uint(a);
    uint32_t r1 = (u + 0x1FFFFFu + ((u >> 22) & 1u)) & 0xFFC00000u;
    float q2 = __fadd_rn(__fadd_rn(a, cM), -cM);
    uint32_t q = (u < c2s_bits) ? __float_as_uint(q2) : r1;
    return __uint_as_float(q | (__float_as_uint(t) & 0x80000000u));
}

// pack two exact f32 values into f16x2 (lo = x, hi = y); conversion exact
__device__ __forceinline__ uint32_t pack_h2(float x, float y) {
    uint32_t r;
    asm("cvt.rn.f16x2.f32 %0, %1, %2;" : "=r"(r) : "f"(y), "f"(x));
    return r;
}

// ---------------------------------------------------------------------------
// x quant-dequant -> f16 (one MXFP block = 8 lanes x float4)
// ---------------------------------------------------------------------------
__global__ void qdq_x_kernel(const float* __restrict__ in) {
    int gtid = blockIdx.x * blockDim.x + threadIdx.x;
    int warp = gtid >> 5;
    int lane = threadIdx.x & 31;
    long base = (long)warp * 128 + (long)lane * 4;
    if (base >= NUM_T * DIN) return;
    float4 v = *reinterpret_cast<const float4*>(in + base);
    float am = fmaxf(fmaxf(fabsf(v.x), fabsf(v.y)), fmaxf(fabsf(v.z), fabsf(v.w)));
    am = fmaxf(am, __shfl_xor_sync(0xffffffffu, am, 1));
    am = fmaxf(am, __shfl_xor_sync(0xffffffffu, am, 2));
    am = fmaxf(am, __shfl_xor_sync(0xffffffffu, am, 4));
    float c6s, cM; uint32_t c2sb;
    mk_consts(am, c6s, cM, c2sb);
    uint2 st;
    st.x = pack_h2(qdq_fast(v.x, c6s, cM, c2sb), qdq_fast(v.y, c6s, cM, c2sb));
    st.y = pack_h2(qdq_fast(v.z, c6s, cM, c2sb), qdq_fast(v.w, c6s, cM, c2sb));
    *reinterpret_cast<uint2*>(&g_xq[base]) = st;
}

// ---------------------------------------------------------------------------
// Fused GEMM (R5 structure) + cp.async raw-W streaming ring (3 deep).
// Each thread owns an 80B raw slot: cp.asyncs its 64B of W 3 chunks ahead,
// LDS-reads it back itself (no barrier needed on the raw ring).
// ---------------------------------------------------------------------------
#define LDMATRIX_X4(r0, r1, r2, r3, addr)                                        \
    asm volatile("ldmatrix.sync.aligned.m8n8.x4.shared.b16 {%0,%1,%2,%3}, [%4];" \
                 : "=r"(r0), "=r"(r1), "=r"(r2), "=r"(r3) : "r"(addr))

#define MMA16816(c, a0, a1, a2, a3, b0, b1)                                   \
    asm volatile("mma.sync.aligned.m16n8k16.row.col.f32.f16.f16.f32 "         \
                 "{%0,%1,%2,%3}, {%4,%5,%6,%7}, {%8,%9}, {%0,%1,%2,%3};"      \
                 : "+f"(c[0]), "+f"(c[1]), "+f"(c[2]), "+f"(c[3])             \
                 : "r"(a0), "r"(a1), "r"(a2), "r"(a3), "r"(b0), "r"(b1))

__global__ __launch_bounds__(256) void fused_gemm_kernel(const float* __restrict__ W) {
    extern __shared__ char smem[];
    __half* smh = reinterpret_cast<__half*>(smem);
    int tid  = threadIdx.x;
    int w    = tid >> 5;
    int lane = tid & 31;
    int nbase = blockIdx.x * NT;
    int kbase = blockIdx.y * KPER;
    int mrow  = (w >> 1) * 16;
    int ncol  = (w & 1) * 32;

    float acc[4][4];
    #pragma unroll
    for (int i = 0; i < 4; i++)
        #pragma unroll
        for (int j = 0; j < 4; j++) acc[i][j] = 0.0f;

    int q = lane >> 3, li = lane & 7;
    uint32_t smem_u32 = (uint32_t)__cvta_generic_to_shared(smem);
    uint32_t a_base = smem_u32 +
        ((mrow + (q & 1) * 8 + li) * SSTRIDE + (q >> 1) * 8) * 2;
    uint32_t b_base = smem_u32 + XW_OFF +
        ((ncol + (q >> 1) * 8 + li) * SSTRIDE + (q & 1) * 8) * 2;

    // W map: 4 threads per row, 16 consecutive floats each (half a 32-block)
    int wrow = tid >> 2;
    int wk   = (tid & 3) << 4;
    const float* wp = W + (size_t)(nbase + wrow) * DIN + kbase + wk;
    // raw slot (bytes): thread-private 80B per stage
    uint32_t raw_slot = smem_u32 + RAW_OFF + tid * 80;
    float* raw_slot_p = reinterpret_cast<float*>(smem + RAW_OFF + tid * 80);
    // X map: 2 uint4 per thread (R5)
    int xr0 = tid >> 3,         xc0 = (tid & 7) * 8;
    int xr1 = (tid + 256) >> 3, xc1 = (tid & 7) * 8;
    const __half* xp0 = &g_xq[xr0 * DIN + kbase + xc0];
    const __half* xp1 = &g_xq[xr1 * DIN + kbase + xc1];

    uint4 xv0, xv1;

    // cp.async thread's 64B of W chunk c into ring slot c%3
    auto cpasync_w = [&](int c) {
        uint32_t d = raw_slot + (c % 3) * RAW_STAGE_B;
        const float* s = wp + c * KC;
        asm volatile(
            "cp.async.cg.shared.global [%0], [%1], 16;\n\t"
            "cp.async.cg.shared.global [%2], [%3], 16;\n\t"
            "cp.async.cg.shared.global [%4], [%5], 16;\n\t"
            "cp.async.cg.shared.global [%6], [%7], 16;\n\t"
            "cp.async.commit_group;"
            :: "r"(d), "l"(s), "r"(d + 16), "l"(s + 4),
               "r"(d + 32), "l"(s + 8), "r"(d + 48), "l"(s + 12) : "memory");
    };

    // read raw chunk c from own slot, quantize, store to f16 stage (c&1)
    auto stagec = [&](int c) {
        float* rp = reinterpret_cast<float*>(
            reinterpret_cast<char*>(raw_slot_p) + (c % 3) * RAW_STAGE_B);
        float4 wv[4];
        #pragma unroll
        for (int j = 0; j < 4; j++)
            wv[j] = reinterpret_cast<const float4*>(rp)[j];
        int s = c & 1;
        __half* Xs = smh + s * (F16_STAGE_B / 2);
        __half* Ws = Xs + XW_OFF / 2;
        *reinterpret_cast<uint4*>(&Xs[xr0 * SSTRIDE + xc0]) = xv0;
        *reinterpret_cast<uint4*>(&Xs[xr1 * SSTRIDE + xc1]) = xv1;
        float am = 0.0f;
        #pragma unroll
        for (int j = 0; j < 4; j++)
            am = fmaxf(am, fmaxf(fmaxf(fabsf(wv[j].x), fabsf(wv[j].y)),
                                 fmaxf(fabsf(wv[j].z), fabsf(wv[j].w))));
        am = fmaxf(am, __shfl_xor_sync(0xffffffffu, am, 1));   // pair -> 32-block amax
        float c6s, cM; uint32_t c2sb;
        mk_consts(am, c6s, cM, c2sb);
        uint4 s0, s1;
        s0.x = pack_h2(qdq_fast(wv[0].x, c6s, cM, c2sb), qdq_fast(wv[0].y, c6s, cM, c2sb));
        s0.y = pack_h2(qdq_fast(wv[0].z, c6s, cM, c2sb), qdq_fast(wv[0].w, c6s, cM, c2sb));
        s0.z = pack_h2(qdq_fast(wv[1].x, c6s, cM, c2sb), qdq_fast(wv[1].y, c6s, cM, c2sb));
        s0.w = pack_h2(qdq_fast(wv[1].z, c6s, cM, c2sb), qdq_fast(wv[1].w, c6s, cM, c2sb));
        s1.x = pack_h2(qdq_fast(wv[2].x, c6s, cM, c2sb), qdq_fast(wv[2].y, c6s, cM, c2sb));
        s1.y = pack_h2(qdq_fast(wv[2].z, c6s, cM, c2sb), qdq_fast(wv[2].w, c6s, cM, c2sb));
        s1.z = pack_h2(qdq_fast(wv[3].x, c6s, cM, c2sb), qdq_fast(wv[3].y, c6s, cM, c2sb));
        s1.w = pack_h2(qdq_fast(wv[3].z, c6s, cM, c2sb), qdq_fast(wv[3].w, c6s, cM, c2sb));
        *reinterpret_cast<uint4*>(&Ws[wrow * SSTRIDE + wk])     = s0;
        *reinterpret_cast<uint4*>(&Ws[wrow * SSTRIDE + wk + 8]) = s1;
    };

    // -------- prologue: raws 0,1,2 in flight; stage chunk 0 --------
    cpasync_w(0);
    cpasync_w(1);
    cpasync_w(2);
    xv0 = *reinterpret_cast<const uint4*>(xp0);
    xv1 = *reinterpret_cast<const uint4*>(xp1);
    asm volatile("cp.async.wait_group 2;" ::: "memory");   // raw 0 done
    stagec(0);
    xv0 = *reinterpret_cast<const uint4*>(xp0 + KC);
    xv1 = *reinterpret_cast<const uint4*>(xp1 + KC);
    __syncthreads();

    // -------- main loop: one barrier per chunk --------
    #pragma unroll 1
    for (int c = 0; c < NCHUNK; c++) {
        if (c + 3 < NCHUNK)
            cpasync_w(c + 3);
        if (c + 1 < NCHUNK) {
            if (c < NCHUNK - 3)
                asm volatile("cp.async.wait_group 2;" ::: "memory");
            else if (c == NCHUNK - 3)
                asm volatile("cp.async.wait_group 1;" ::: "memory");
            else
                asm volatile("cp.async.wait_group 0;" ::: "memory");
            stagec(c + 1);
            if (c + 2 < NCHUNK) {
                xv0 = *reinterpret_cast<const uint4*>(xp0 + (c + 2) * KC);
                xv1 = *reinterpret_cast<const uint4*>(xp1 + (c + 2) * KC);
            }
        }
        uint32_t off = (c & 1) * F16_STAGE_B;
        #pragma unroll
        for (int ks = 0; ks < 4; ks++) {
            uint32_t a0, a1, a2, a3;
            LDMATRIX_X4(a0, a1, a2, a3, a_base + off + ks * 32);
            #pragma unroll
            for (int nb = 0; nb < 2; nb++) {
                uint32_t b0, b1, b2, b3;
                LDMATRIX_X4(b0, b1, b2, b3,
                            b_base + off + nb * (16 * SSTRIDE * 2) + ks * 32);
                MMA16816(acc[nb * 2 + 0], a0, a1, a2, a3, b0, b1);
                MMA16816(acc[nb * 2 + 1], a0, a1, a2, a3, b2, b3);
            }
        }
        __syncthreads();
    }

    // epilogue: fp32 partials (R5 layout)
    float* pb = g_part + (size_t)blockIdx.y * NUM_T * DOUT;
    int tg = lane >> 2, tig = lane & 3;
    #pragma unroll
    for (int nf = 0; nf < 4; nf++) {
        int col = nbase + ncol + nf * 8 + tig * 2;
        int r0  = mrow + tg;
        *reinterpret_cast<float2*>(&pb[(size_t)r0 * DOUT + col]) =
            make_float2(acc[nf][0], acc[nf][1]);
        *reinterpret_cast<float2*>(&pb[(size_t)(r0 + 8) * DOUT + col]) =
            make_float2(acc[nf][2], acc[nf][3]);
    }
}

// ---------------------------------------------------------------------------
// Reduce K-splits + bias qdq. 1 thread = 1 float4 of output.
// ---------------------------------------------------------------------------
__global__ void reduce_bias_kernel(const float* __restrict__ bias, float* __restrict__ out) {
    int t  = blockIdx.x * blockDim.x + threadIdx.x;
    int m  = t / (DOUT / 4);
    int o  = (t % (DOUT / 4)) * 4;

    float4 b4 = *reinterpret_cast<const float4*>(bias + o);
    float am = fmaxf(fmaxf(fabsf(b4.x), fabsf(b4.y)), fmaxf(fabsf(b4.z), fabsf(b4.w)));
    am = fmaxf(am, __shfl_xor_sync(0xffffffffu, am, 1));
    am = fmaxf(am, __shfl_xor_sync(0xffffffffu, am, 2));
    am = fmaxf(am, __shfl_xor_sync(0xffffffffu, am, 4));
    float c6s, cM; uint32_t c2sb;
    mk_consts(am, c6s, cM, c2sb);

    size_t idx = (size_t)m * DOUT + o;
    const size_t ps = (size_t)NUM_T * DOUT;
    float4 r;
    r.x = qdq_fast(b4.x, c6s, cM, c2sb);
    r.y = qdq_fast(b4.y, c6s, cM, c2sb);
    r.z = qdq_fast(b4.z, c6s, cM, c2sb);
    r.w = qdq_fast(b4.w, c6s, cM, c2sb);
    #pragma unroll
    for (int s = 0; s < KS; s++) {
        float4 p = *reinterpret_cast<const float4*>(g_part + s * ps + idx);
        r.x += p.x; r.y += p.y; r.z += p.z; r.w += p.w;
    }
    *reinterpret_cast<float4*>(out + idx) = r;
}

// ---------------------------------------------------------------------------
extern "C" void kernel_launch(void* const* d_in, const int* in_sizes, int n_in,
                              void* d_out, int out_size) {
    const float* x = nullptr;
    const float* wgt = nullptr;
    const float* bias = nullptr;
    for (int i = 0; i < n_in; i++) {
        if (in_sizes[i] == NUM_T * DIN)     x    = (const float*)d_in[i];
        else if (in_sizes[i] == DOUT * DIN) wgt  = (const float*)d_in[i];
        else if (in_sizes[i] == DOUT)       bias = (const float*)d_in[i];
    }
    float* out = (float*)d_out;

    cudaFuncSetAttribute(fused_gemm_kernel,
                         cudaFuncAttributeMaxDynamicSharedMemorySize, SMEM_TOTAL);

    qdq_x_kernel<<<NUM_T * DIN / 4 / 128, 128>>>(x);
    fused_gemm_kernel<<<dim3(DOUT / NT, KS), 256, SMEM_TOTAL>>>(wgt);
    reduce_bias_kernel<<<(NUM_T * DOUT / 4) / 256, 256>>>(bias, out);
    (void)out_size;
}